// round 12
// baseline (speedup 1.0000x reference)
#include <cuda_runtime.h>
#include <cuda_bf16.h>

// Problem constants (fixed shapes from reference setup_inputs)
#define N_ 32768
#define K_ 4096
#define D_ 256

// ---------------- device scratch (no allocations allowed) ----------------
__device__ float  g_x2[N_];           // ||x_n||^2 (XLA-style warp row-reduce bits)
__device__ float  g_e2a[K_];          // ||embedding_k||^2 (pass A)
__device__ float  g_e2b[K_];          // ||new_embedding_k||^2 (pass B)
__device__ __align__(16) float g_embB[K_ * D_];   // aligned copy of new_embedding for pass B
__device__ int    g_idx1[N_];         // argmin pass A
__device__ int    g_idx2[N_];         // argmin pass B
__device__ float  g_counts[K_];       // segment counts (pass A)
__device__ float  g_dw[K_ * D_];      // segment sum of x per code
__device__ double g_loss_part[256];   // partial commitment-loss sums
__device__ float  g_nsum;             // sum(new_cs)
__device__ int    g_used[K_];         // used mask from pass B
__device__ int    g_usage_cnt;        // count(new_usage > 0)

// ---------------- helpers ----------------
__device__ __forceinline__ unsigned long long pack_min(float f, int idx) {
    unsigned u = __float_as_uint(f);
    u = (u & 0x80000000u) ? ~u : (u | 0x80000000u);   // order-preserving key
    return ((unsigned long long)u << 32) | (unsigned)idx;
}

// packed 2xfp32 FMA (each lane rounds .rn, bit-identical to scalar FFMA)
__device__ __forceinline__ unsigned long long ffma2(unsigned long long a,
                                                    unsigned long long b,
                                                    unsigned long long c) {
    unsigned long long d;
    asm("fma.rn.f32x2 %0, %1, %2, %3;" : "=l"(d) : "l"(a), "l"(b), "l"(c));
    return d;
}

// duplicate one float into both halves of a 64-bit pair
__device__ __forceinline__ unsigned long long pack2(float v) {
    unsigned long long r;
    asm("mov.b64 %0, {%1, %1};" : "=l"(r) : "f"(v));
    return r;
}

__device__ __forceinline__ void cp_async16(unsigned dst, const void* src) {
    asm volatile("cp.async.cg.shared.global [%0], [%1], 16;" :: "r"(dst), "l"(src));
}
__device__ __forceinline__ void cp_commit() {
    asm volatile("cp.async.commit_group;");
}
__device__ __forceinline__ void cp_wait0() {
    asm volatile("cp.async.wait_group 0;" ::: "memory");
}

// ---------------- init: zero all scratch (graph replays!) ----------------
__global__ void init_kernel() {
    int i = blockIdx.x * blockDim.x + threadIdx.x;
    g_dw[i] = 0.0f;
    if (i < K_) { g_counts[i] = 0.0f; g_used[i] = 0; }
    if (i < 256) g_loss_part[i] = 0.0;
    if (i == 0) { g_nsum = 0.0f; g_usage_cnt = 0; }
}

// ---------------- row sum-of-squares, XLA-style warp reduce ----------------
__global__ void rowsq_kernel(const float* __restrict__ X, float* __restrict__ out, int rows) {
    int warp = (blockIdx.x * blockDim.x + threadIdx.x) >> 5;
    int lane = threadIdx.x & 31;
    if (warp >= rows) return;
    const float* row = X + (size_t)warp * D_;
    float acc = 0.0f;
    #pragma unroll
    for (int i = 0; i < 8; i++) {
        float v = row[lane + 32 * i];
        acc = __fadd_rn(acc, __fmul_rn(v, v));
    }
    #pragma unroll
    for (int o = 16; o > 0; o >>= 1)
        acc = __fadd_rn(acc, __shfl_down_sync(0xffffffffu, acc, o));
    if (lane == 0) out[warp] = acc;
}

// ---------------- fused distance-argmin SGEMM (FFMA2, cp.async double-buffered B) ----------------
// score[n,k] = fl(fl(x2[n] - 2*dot(x_n,E_k)) + e2[k]); argmin over k, lowest-index ties.
// Grid: N/128 = 256 blocks, full K per block (R6 frame). Block: 128 rows stationary in
// smem; B streamed as 256-col x 32-d chunks via cp.async, double-buffered.
// Warp owns 16 consecutive rows (broadcast A reads); lane owns cols lane+32j.
#define AS_STRIDE 132
#define AS_BYTES  (256 * AS_STRIDE * 4)       // 135168
#define BUF_BYTES (256 * 9 * 16)              // 36864 per buffer (256 cols x (8 float4 + pad))
#define X2S_BYTES (128 * 4)
#define SMEM_ARG  (AS_BYTES + 2 * BUF_BYTES + X2S_BYTES)   // 209408

__global__ void __launch_bounds__(256, 1)
argmin_kernel(const float* __restrict__ X, const float* __restrict__ E, int pass)
{
    extern __shared__ __align__(16) char smem[];
    float (*As)[AS_STRIDE] = (float (*)[AS_STRIDE])smem;          // [256 d][128 rows]
    float4* Bs0 = (float4*)(smem + AS_BYTES);                     // [256 cols][9]
    float4* Bs1 = (float4*)(smem + AS_BYTES + BUF_BYTES);
    float* x2s  = (float*)(smem + AS_BYTES + 2 * BUF_BYTES);

    const float* __restrict__ e2 = pass ? g_e2b : g_e2a;
    int* __restrict__ out_idx    = pass ? g_idx2 : g_idx1;

    const int tid  = threadIdx.x;
    const int lane = tid & 31;
    const int warp = tid >> 5;              // 8 warps, warp owns rows warp*16..+16
    const int rowBase = blockIdx.x * 128;

    const unsigned bs_u32 = (unsigned)__cvta_generic_to_shared(smem + AS_BYTES);

    // ---- load A transposed (once): X[rowBase+r][d] -> As[d][r] ----
    // warp w covers d-range w*32..w*32+31; lane indexes the row -> conflict-free STS.
    {
        #pragma unroll
        for (int rr = 0; rr < 4; rr++) {
            int r = rr * 32 + lane;
            const float* src = &X[(size_t)(rowBase + r) * D_ + warp * 32];
            #pragma unroll
            for (int q = 0; q < 8; q++) {
                float4 v = *(const float4*)(src + q * 4);
                As[warp * 32 + q * 4 + 0][r] = v.x;
                As[warp * 32 + q * 4 + 1][r] = v.y;
                As[warp * 32 + q * 4 + 2][r] = v.z;
                As[warp * 32 + q * 4 + 3][r] = v.w;
            }
        }
        if (tid < 128) x2s[tid] = g_x2[rowBase + tid];
    }

    float rmin[16];
    int   ridx[16];
    #pragma unroll
    for (int i = 0; i < 16; i++) { rmin[i] = 3.4e38f; ridx[i] = 0; }

    unsigned long long acc2[8][8];

    // ---- prologue: prefetch chunk 0 (thread owns col=tid, 8x16B contiguous d-block) ----
    {
        const float* src = &E[(size_t)tid * D_];
        unsigned dst = bs_u32 + tid * 144;
        #pragma unroll
        for (int d4 = 0; d4 < 8; d4++) cp_async16(dst + d4 * 16, src + d4 * 4);
        cp_commit();
    }
    cp_wait0();
    __syncthreads();

    // ---- 128 chunks: (16 ct-tiles of 256 cols) x (8 d-chunks of 32) ----
    #pragma unroll 1
    for (int q = 0; q < 128; q++) {
        // issue prefetch of next chunk into the other buffer
        if (q < 127) {
            int qq = q + 1;
            int ctn = (qq >> 3) * 256;
            int dbn = (qq & 7) * 32;
            const float* src = &E[(size_t)(ctn + tid) * D_ + dbn];
            unsigned dst = bs_u32 + (qq & 1) * BUF_BYTES + tid * 144;
            #pragma unroll
            for (int d4 = 0; d4 < 8; d4++) cp_async16(dst + d4 * 16, src + d4 * 4);
            cp_commit();
        }

        if ((q & 7) == 0) {
            #pragma unroll
            for (int i = 0; i < 8; i++)
                #pragma unroll
                for (int j = 0; j < 8; j++) acc2[i][j] = 0ull;
        }

        // compute chunk q from buffer q&1
        {
            const float4* bufp = (q & 1) ? Bs1 : Bs0;
            const int dbase = (q & 7) * 32;
            #pragma unroll
            for (int d4 = 0; d4 < 8; d4++) {
                float4 bb[8];
                #pragma unroll
                for (int j = 0; j < 8; j++)
                    bb[j] = bufp[(lane + 32 * j) * 9 + d4];   // pad -> conflict-free phases
                #pragma unroll
                for (int dr = 0; dr < 4; dr++) {
                    const ulonglong2* ap =
                        (const ulonglong2*)&As[dbase + d4 * 4 + dr][warp * 16];
                    ulonglong2 p0 = ap[0], p1 = ap[1], p2 = ap[2], p3 = ap[3];
                    unsigned long long a2[8];
                    a2[0] = p0.x; a2[1] = p0.y; a2[2] = p1.x; a2[3] = p1.y;
                    a2[4] = p2.x; a2[5] = p2.y; a2[6] = p3.x; a2[7] = p3.y;
                    #pragma unroll
                    for (int j = 0; j < 8; j++) {
                        float bv = (dr == 0) ? bb[j].x : (dr == 1) ? bb[j].y
                                 : (dr == 2) ? bb[j].z : bb[j].w;
                        unsigned long long b2 = pack2(bv);
                        #pragma unroll
                        for (int i = 0; i < 8; i++)
                            acc2[i][j] = ffma2(a2[i], b2, acc2[i][j]);
                    }
                }
            }
        }

        // fold completed ct-tile into running argmin (exact reference rounding)
        if ((q & 7) == 7) {
            int ct = (q >> 3) * 256;
            #pragma unroll
            for (int j = 0; j < 8; j++) {
                int col = ct + lane + 32 * j;
                float ev = __ldg(&e2[col]);
                #pragma unroll
                for (int i = 0; i < 8; i++) {
                    float xlo = x2s[warp * 16 + 2 * i];
                    float xhi = x2s[warp * 16 + 2 * i + 1];
                    float mlo = __uint_as_float((unsigned)(acc2[i][j] & 0xffffffffull));
                    float mhi = __uint_as_float((unsigned)(acc2[i][j] >> 32));
                    float sc0 = __fadd_rn(__fadd_rn(xlo, __fmul_rn(-2.0f, mlo)), ev);
                    float sc1 = __fadd_rn(__fadd_rn(xhi, __fmul_rn(-2.0f, mhi)), ev);
                    if (sc0 < rmin[2 * i])     { rmin[2 * i] = sc0;     ridx[2 * i] = col; }
                    if (sc1 < rmin[2 * i + 1]) { rmin[2 * i + 1] = sc1; ridx[2 * i + 1] = col; }
                }
            }
        }

        cp_wait0();
        __syncthreads();
    }

    // ---- cross-lane reduce: each row's 32 lane-partials, lowest index on ties ----
    #pragma unroll
    for (int rr = 0; rr < 16; rr++) {
        unsigned long long b = pack_min(rmin[rr], ridx[rr]);
        #pragma unroll
        for (int o = 16; o > 0; o >>= 1) {
            unsigned long long v = __shfl_xor_sync(0xffffffffu, b, o);
            if (v < b) b = v;
        }
        if (lane == 0) out_idx[rowBase + warp * 16 + rr] = (int)(b & 0xffffffffu);
    }
}

// ---------------- quantize + loss + segment sums (pass A) ----------------
__global__ void stats_kernel(const float* __restrict__ X, const float* __restrict__ E,
                             float* __restrict__ out_quant, float* __restrict__ out_idxf)
{
    int n = blockIdx.x;
    int d = threadIdx.x;
    int idx = g_idx1[n];
    float xv = X[(size_t)n * D_ + d];
    float q  = E[(size_t)idx * D_ + d];
    float quant = __fadd_rn(xv, __fadd_rn(q, -xv));   // fl(x + fl(q - x))
    out_quant[(size_t)n * D_ + d] = quant;
    float diff = __fadd_rn(xv, -quant);
    float v = __fmul_rn(diff, diff);
    __shared__ float sh[8];
    #pragma unroll
    for (int o = 16; o > 0; o >>= 1) v += __shfl_down_sync(0xffffffffu, v, o);
    if ((d & 31) == 0) sh[d >> 5] = v;
    __syncthreads();
    atomicAdd(&g_dw[(size_t)idx * D_ + d], xv);
    if (d == 0) {
        float s = 0.0f;
        #pragma unroll
        for (int w = 0; w < 8; w++) s += sh[w];
        atomicAdd(&g_loss_part[n & 255], (double)s);
        out_idxf[n] = (float)idx;
        atomicAdd(&g_counts[idx], 1.0f);
    }
}

// ---------------- new_cs, new_usage, n-sum, usage count ----------------
__global__ void cs_kernel(const float* __restrict__ ema_cs, const float* __restrict__ usage,
                          float* __restrict__ out_cs, float* __restrict__ out_usage)
{
    int k = blockIdx.x * 256 + threadIdx.x;   // grid = 16
    float c = g_counts[k];
    float ncs = __fadd_rn(__fmul_rn(ema_cs[k], 0.99f), __fmul_rn(0.01f, c));
    out_cs[k] = ncs;
    float nu = __fadd_rn(__fmul_rn(usage[k], 0.99f), __fmul_rn(0.01f, c));
    out_usage[k] = nu;

    float v = ncs;
    __shared__ float sh[8];
    #pragma unroll
    for (int o = 16; o > 0; o >>= 1) v += __shfl_down_sync(0xffffffffu, v, o);
    if ((threadIdx.x & 31) == 0) sh[threadIdx.x >> 5] = v;

    unsigned bal = __ballot_sync(0xffffffffu, nu > 0.0f);
    if ((threadIdx.x & 31) == 0) atomicAdd(&g_usage_cnt, __popc(bal));

    __syncthreads();
    if (threadIdx.x == 0) {
        float s = 0.0f;
        #pragma unroll
        for (int w = 0; w < 8; w++) s += sh[w];
        atomicAdd(&g_nsum, s);
    }
}

// ---------------- new_ema_w, new_embedding (to out + aligned scratch) ----------------
__global__ void emb_kernel(const float* __restrict__ ema_w, const float* __restrict__ out_cs,
                           float* __restrict__ out_ema_w, float* __restrict__ out_emb)
{
    int k = blockIdx.x;
    int d = threadIdx.x;
    float ncs = out_cs[k];
    float n = g_nsum;
    float csz = __fmul_rn(__fdiv_rn(__fadd_rn(ncs, 1e-5f),
                                    __fadd_rn(n, (float)K_ * 1e-5f)), n);
    float w = __fadd_rn(__fmul_rn(ema_w[(size_t)k * D_ + d], 0.99f),
                        __fmul_rn(0.01f, g_dw[(size_t)k * D_ + d]));
    out_ema_w[(size_t)k * D_ + d] = w;
    float e = __fdiv_rn(w, csz);
    out_emb[(size_t)k * D_ + d] = e;
    g_embB[(size_t)k * D_ + d] = e;            // aligned copy for pass-B argmin
}

// ---------------- scalars: loss, usage_rate ----------------
__global__ void scalar_kernel(float* __restrict__ out_loss, float* __restrict__ out_urate) {
    double s = 0.0;
    for (int i = 0; i < 256; i++) s += g_loss_part[i];
    *out_loss = 0.25f * (float)(s / ((double)N_ * (double)D_));
    *out_urate = (float)g_usage_cnt / (float)K_;
}

// ---------------- used mask from pass B ----------------
__global__ void used_kernel() {
    int i = blockIdx.x * 256 + threadIdx.x;   // grid = 128
    g_used[g_idx2[i]] = 1;
}

// ---------------- dead-code reset + steps output ----------------
__global__ void finalize_kernel(const float* __restrict__ X, const int* __restrict__ steps_in,
                                const int* __restrict__ rnd, float* __restrict__ out_emb,
                                float* __restrict__ out_steps)
{
    int k = blockIdx.x;
    int d = threadIdx.x;
    int used = g_used[k];
    float stepv = used ? 0.0f : ((float)steps_in[k] + 1.0f);
    bool dead = stepv > 100.0f;
    if (dead) {
        int r = rnd[k];
        out_emb[(size_t)k * D_ + d] = X[(size_t)r * D_ + d];
    }
    if (d == 0) out_steps[k] = dead ? 0.0f : stepv;
}

// ---------------- launch ----------------
extern "C" void kernel_launch(void* const* d_in, const int* in_sizes, int n_in,
                              void* d_out, int out_size)
{
    const float* x       = (const float*)d_in[0];
    const float* emb     = (const float*)d_in[1];
    const float* ema_cs  = (const float*)d_in[2];
    const float* ema_w   = (const float*)d_in[3];
    const float* usage   = (const float*)d_in[4];
    const int*   steps_i = (const int*)d_in[5];
    const int*   rnd     = (const int*)d_in[6];

    float* out     = (float*)d_out;
    float* o_quant = out;                         // N*D
    float* o_idx   = o_quant + (size_t)N_ * D_;   // N
    float* o_loss  = o_idx + N_;                  // 1
    float* o_emb   = o_loss + 1;                  // K*D (only 4B-aligned; scalar access only)
    float* o_cs    = o_emb + (size_t)K_ * D_;     // K
    float* o_emaw  = o_cs + K_;                   // K*D
    float* o_usage = o_emaw + (size_t)K_ * D_;    // K
    float* o_steps = o_usage + K_;                // K
    float* o_urate = o_steps + K_;                // 1

    float* embB_dev = nullptr;
    cudaGetSymbolAddress((void**)&embB_dev, g_embB);
    float* x2_dev = nullptr;
    cudaGetSymbolAddress((void**)&x2_dev, g_x2);
    float* e2a_dev = nullptr;
    cudaGetSymbolAddress((void**)&e2a_dev, g_e2a);
    float* e2b_dev = nullptr;
    cudaGetSymbolAddress((void**)&e2b_dev, g_e2b);

    static int smem_configured = 0;
    if (!smem_configured) {
        cudaFuncSetAttribute(argmin_kernel,
                             cudaFuncAttributeMaxDynamicSharedMemorySize, SMEM_ARG);
        smem_configured = 1;
    }

    init_kernel<<<(K_ * D_) / 256, 256>>>();
    rowsq_kernel<<<N_ / 8, 256>>>(x, x2_dev, N_);          // x2 (bit-critical)
    rowsq_kernel<<<K_ / 8, 256>>>(emb, e2a_dev, K_);       // e2 pass A
    argmin_kernel<<<N_ / 128, 256, SMEM_ARG>>>(x, emb, 0);
    stats_kernel<<<N_, 256>>>(x, emb, o_quant, o_idx);
    cs_kernel<<<K_ / 256, 256>>>(ema_cs, usage, o_cs, o_usage);
    emb_kernel<<<K_, 256>>>(ema_w, o_cs, o_emaw, o_emb);
    scalar_kernel<<<1, 1>>>(o_loss, o_urate);
    rowsq_kernel<<<K_ / 8, 256>>>(embB_dev, e2b_dev, K_);  // e2 pass B
    argmin_kernel<<<N_ / 128, 256, SMEM_ARG>>>(x, embB_dev, 1);
    used_kernel<<<N_ / 256, 256>>>();
    finalize_kernel<<<K_, 256>>>(x, steps_i, rnd, o_emb, o_steps);
}

// round 14
// speedup vs baseline: 1.3226x; 1.3226x over previous
#include <cuda_runtime.h>
#include <cuda_bf16.h>

// Problem constants (fixed shapes from reference setup_inputs)
#define N_ 32768
#define K_ 4096
#define D_ 256

// ---------------- device scratch (no allocations allowed) ----------------
__device__ float  g_x2[N_];           // ||x_n||^2 (XLA-style warp row-reduce bits)
__device__ float  g_e2a[K_];          // ||embedding_k||^2 (pass A)
__device__ float  g_e2b[K_];          // ||new_embedding_k||^2 (pass B)
__device__ __align__(16) float g_embB[K_ * D_];   // aligned copy of new_embedding for pass B
__device__ int    g_idx1[N_];         // argmin pass A
__device__ int    g_idx2[N_];         // argmin pass B
__device__ float  g_counts[K_];       // segment counts (pass A)
__device__ float  g_dw[K_ * D_];      // segment sum of x per code
__device__ double g_loss_part[256];   // partial commitment-loss sums
__device__ float  g_nsum;             // sum(new_cs)
__device__ int    g_used[K_];         // used mask from pass B
__device__ int    g_usage_cnt;        // count(new_usage > 0)

// ---------------- helpers ----------------
__device__ __forceinline__ unsigned long long pack_min(float f, int idx) {
    unsigned u = __float_as_uint(f);
    u = (u & 0x80000000u) ? ~u : (u | 0x80000000u);   // order-preserving key
    return ((unsigned long long)u << 32) | (unsigned)idx;
}

// packed 2xfp32 FMA (each lane rounds .rn, bit-identical to scalar FFMA)
__device__ __forceinline__ unsigned long long ffma2(unsigned long long a,
                                                    unsigned long long b,
                                                    unsigned long long c) {
    unsigned long long d;
    asm("fma.rn.f32x2 %0, %1, %2, %3;" : "=l"(d) : "l"(a), "l"(b), "l"(c));
    return d;
}

// duplicate one float into both halves of a 64-bit pair
__device__ __forceinline__ unsigned long long pack2(float v) {
    unsigned long long r;
    asm("mov.b64 %0, {%1, %1};" : "=l"(r) : "f"(v));
    return r;
}

// ---------------- init: zero all scratch (graph replays!) ----------------
__global__ void init_kernel() {
    int i = blockIdx.x * blockDim.x + threadIdx.x;
    g_dw[i] = 0.0f;
    if (i < K_) { g_counts[i] = 0.0f; g_used[i] = 0; }
    if (i < 256) g_loss_part[i] = 0.0;
    if (i == 0) { g_nsum = 0.0f; g_usage_cnt = 0; }
}

// ---------------- row sum-of-squares, XLA-style warp reduce ----------------
__global__ void rowsq_kernel(const float* __restrict__ X, float* __restrict__ out, int rows) {
    int warp = (blockIdx.x * blockDim.x + threadIdx.x) >> 5;
    int lane = threadIdx.x & 31;
    if (warp >= rows) return;
    const float* row = X + (size_t)warp * D_;
    float acc = 0.0f;
    #pragma unroll
    for (int i = 0; i < 8; i++) {
        float v = row[lane + 32 * i];
        acc = __fadd_rn(acc, __fmul_rn(v, v));
    }
    #pragma unroll
    for (int o = 16; o > 0; o >>= 1)
        acc = __fadd_rn(acc, __shfl_down_sync(0xffffffffu, acc, o));
    if (lane == 0) out[warp] = acc;
}

// ---------------- fused distance-argmin SGEMM (FFMA2, X-stationary, 512 threads) ----------------
// score[n,k] = fl(fl(x2[n] - 2*dot(x_n,E_k)) + e2[k]); argmin over k, lowest-index ties.
// Grid: N/128 = 256 blocks, full K per block. Block: 512 threads (16 warps), 128 rows
// stationary in smem; B streamed as 256-col x 32-d chunks. Warp owns 8 consecutive rows
// (broadcast A reads); lane owns 8 consecutive cols. 4 warps/SMSP hide LDS/barrier latency.
#define AS_STRIDE 132
#define AS_BYTES  (256 * AS_STRIDE * 4)   // 135168
#define BS_BYTES  (32 * 256 * 4)          // 32768
#define X2S_BYTES (128 * 4)
#define SMEM_ARG  (AS_BYTES + BS_BYTES + X2S_BYTES)   // 168448

__global__ void __launch_bounds__(512, 1)
argmin_kernel(const float* __restrict__ X, const float* __restrict__ E, int pass)
{
    extern __shared__ __align__(16) char smem[];
    float (*As)[AS_STRIDE] = (float (*)[AS_STRIDE])smem;          // [256 d][128 rows]
    float (*Bs)[256]       = (float (*)[256])(smem + AS_BYTES);   // [32 d][256 cols]
    float* x2s             = (float*)(smem + AS_BYTES + BS_BYTES);

    const float* __restrict__ e2 = pass ? g_e2b : g_e2a;
    int* __restrict__ out_idx    = pass ? g_idx2 : g_idx1;

    const int tid  = threadIdx.x;
    const int lane = tid & 31;
    const int warp = tid >> 5;           // 16 warps, warp owns rows warp*8..+8
    const int rowBase = blockIdx.x * 128;

    // ---- load A transposed (once): X[rowBase+r][d] -> As[d][r] ----
    // warp w covers d-range w*16..w*16+16; lane indexes the row -> conflict-free STS.
    {
        #pragma unroll
        for (int rr = 0; rr < 4; rr++) {
            int r = rr * 32 + lane;
            const float* src = &X[(size_t)(rowBase + r) * D_ + warp * 16];
            #pragma unroll
            for (int q = 0; q < 4; q++) {
                float4 v = *(const float4*)(src + q * 4);
                As[warp * 16 + q * 4 + 0][r] = v.x;
                As[warp * 16 + q * 4 + 1][r] = v.y;
                As[warp * 16 + q * 4 + 2][r] = v.z;
                As[warp * 16 + q * 4 + 3][r] = v.w;
            }
        }
        if (tid < 128) x2s[tid] = g_x2[rowBase + tid];
    }

    float rmin[8];
    int   ridx[8];
    #pragma unroll
    for (int i = 0; i < 8; i++) { rmin[i] = 3.4e38f; ridx[i] = 0; }

    for (int ct = 0; ct < K_; ct += 256) {
        unsigned long long acc2[4][8];
        #pragma unroll
        for (int i = 0; i < 4; i++)
            #pragma unroll
            for (int j = 0; j < 8; j++) acc2[i][j] = 0ull;

        for (int d0 = 0; d0 < D_; d0 += 32) {
            __syncthreads();   // prev chunk consumed (also orders A-load on first pass)
            // load B chunk: two threads per col, each 16 d; conflict-free STS.
            {
                int c  = tid & 255;
                int dh = (tid >> 8) * 16;
                const float* src = &E[(size_t)(ct + c) * D_ + d0 + dh];
                #pragma unroll
                for (int q = 0; q < 4; q++) {
                    float4 u = *(const float4*)(src + q * 4);
                    Bs[dh + q * 4 + 0][c] = u.x;
                    Bs[dh + q * 4 + 1][c] = u.y;
                    Bs[dh + q * 4 + 2][c] = u.z;
                    Bs[dh + q * 4 + 3][c] = u.w;
                }
            }
            __syncthreads();
            #pragma unroll 4
            for (int d = 0; d < 32; d++) {
                const ulonglong2* ap = (const ulonglong2*)&As[d0 + d][warp * 8];
                ulonglong2 p0 = ap[0], p1 = ap[1];
                unsigned long long a2[4];
                a2[0] = p0.x; a2[1] = p0.y; a2[2] = p1.x; a2[3] = p1.y;
                float4 bb0 = *(const float4*)&Bs[d][lane * 8];
                float4 bb1 = *(const float4*)&Bs[d][lane * 8 + 4];
                unsigned long long b2[8];
                b2[0] = pack2(bb0.x); b2[1] = pack2(bb0.y);
                b2[2] = pack2(bb0.z); b2[3] = pack2(bb0.w);
                b2[4] = pack2(bb1.x); b2[5] = pack2(bb1.y);
                b2[6] = pack2(bb1.z); b2[7] = pack2(bb1.w);
                #pragma unroll
                for (int i = 0; i < 4; i++)
                    #pragma unroll
                    for (int j = 0; j < 8; j++)
                        acc2[i][j] = ffma2(a2[i], b2[j], acc2[i][j]);
            }
        }
        // ---- fold this 256-col tile into running argmin (exact reference rounding) ----
        float xv[8];
        #pragma unroll
        for (int i = 0; i < 8; i++) xv[i] = x2s[warp * 8 + i];
        #pragma unroll
        for (int j = 0; j < 8; j++) {
            int col = ct + lane * 8 + j;
            float ev = __ldg(&e2[col]);
            #pragma unroll
            for (int i = 0; i < 4; i++) {
                float mlo = __uint_as_float((unsigned)(acc2[i][j] & 0xffffffffull));
                float mhi = __uint_as_float((unsigned)(acc2[i][j] >> 32));
                float sc0 = __fadd_rn(__fadd_rn(xv[2 * i],     __fmul_rn(-2.0f, mlo)), ev);
                float sc1 = __fadd_rn(__fadd_rn(xv[2 * i + 1], __fmul_rn(-2.0f, mhi)), ev);
                if (sc0 < rmin[2 * i])     { rmin[2 * i] = sc0;     ridx[2 * i] = col; }
                if (sc1 < rmin[2 * i + 1]) { rmin[2 * i + 1] = sc1; ridx[2 * i + 1] = col; }
            }
        }
    }

    // ---- cross-lane reduce: each row's 32 lane-partials, lowest index on ties ----
    #pragma unroll
    for (int rr = 0; rr < 8; rr++) {
        unsigned long long b = pack_min(rmin[rr], ridx[rr]);
        #pragma unroll
        for (int o = 16; o > 0; o >>= 1) {
            unsigned long long v = __shfl_xor_sync(0xffffffffu, b, o);
            if (v < b) b = v;
        }
        if (lane == 0) out_idx[rowBase + warp * 8 + rr] = (int)(b & 0xffffffffu);
    }
}

// ---------------- quantize + loss + segment sums (pass A) ----------------
__global__ void stats_kernel(const float* __restrict__ X, const float* __restrict__ E,
                             float* __restrict__ out_quant, float* __restrict__ out_idxf)
{
    int n = blockIdx.x;
    int d = threadIdx.x;
    int idx = g_idx1[n];
    float xv = X[(size_t)n * D_ + d];
    float q  = E[(size_t)idx * D_ + d];
    float quant = __fadd_rn(xv, __fadd_rn(q, -xv));   // fl(x + fl(q - x))
    out_quant[(size_t)n * D_ + d] = quant;
    float diff = __fadd_rn(xv, -quant);
    float v = __fmul_rn(diff, diff);
    __shared__ float sh[8];
    #pragma unroll
    for (int o = 16; o > 0; o >>= 1) v += __shfl_down_sync(0xffffffffu, v, o);
    if ((d & 31) == 0) sh[d >> 5] = v;
    __syncthreads();
    atomicAdd(&g_dw[(size_t)idx * D_ + d], xv);
    if (d == 0) {
        float s = 0.0f;
        #pragma unroll
        for (int w = 0; w < 8; w++) s += sh[w];
        atomicAdd(&g_loss_part[n & 255], (double)s);
        out_idxf[n] = (float)idx;
        atomicAdd(&g_counts[idx], 1.0f);
    }
}

// ---------------- new_cs, new_usage, n-sum, usage count ----------------
__global__ void cs_kernel(const float* __restrict__ ema_cs, const float* __restrict__ usage,
                          float* __restrict__ out_cs, float* __restrict__ out_usage)
{
    int k = blockIdx.x * 256 + threadIdx.x;   // grid = 16
    float c = g_counts[k];
    float ncs = __fadd_rn(__fmul_rn(ema_cs[k], 0.99f), __fmul_rn(0.01f, c));
    out_cs[k] = ncs;
    float nu = __fadd_rn(__fmul_rn(usage[k], 0.99f), __fmul_rn(0.01f, c));
    out_usage[k] = nu;

    float v = ncs;
    __shared__ float sh[8];
    #pragma unroll
    for (int o = 16; o > 0; o >>= 1) v += __shfl_down_sync(0xffffffffu, v, o);
    if ((threadIdx.x & 31) == 0) sh[threadIdx.x >> 5] = v;

    unsigned bal = __ballot_sync(0xffffffffu, nu > 0.0f);
    if ((threadIdx.x & 31) == 0) atomicAdd(&g_usage_cnt, __popc(bal));

    __syncthreads();
    if (threadIdx.x == 0) {
        float s = 0.0f;
        #pragma unroll
        for (int w = 0; w < 8; w++) s += sh[w];
        atomicAdd(&g_nsum, s);
    }
}

// ---------------- new_ema_w, new_embedding (to out + aligned scratch) ----------------
__global__ void emb_kernel(const float* __restrict__ ema_w, const float* __restrict__ out_cs,
                           float* __restrict__ out_ema_w, float* __restrict__ out_emb)
{
    int k = blockIdx.x;
    int d = threadIdx.x;
    float ncs = out_cs[k];
    float n = g_nsum;
    float csz = __fmul_rn(__fdiv_rn(__fadd_rn(ncs, 1e-5f),
                                    __fadd_rn(n, (float)K_ * 1e-5f)), n);
    float w = __fadd_rn(__fmul_rn(ema_w[(size_t)k * D_ + d], 0.99f),
                        __fmul_rn(0.01f, g_dw[(size_t)k * D_ + d]));
    out_ema_w[(size_t)k * D_ + d] = w;
    float e = __fdiv_rn(w, csz);
    out_emb[(size_t)k * D_ + d] = e;
    g_embB[(size_t)k * D_ + d] = e;            // aligned copy for pass-B argmin
}

// ---------------- scalars: loss, usage_rate ----------------
__global__ void scalar_kernel(float* __restrict__ out_loss, float* __restrict__ out_urate) {
    double s = 0.0;
    for (int i = 0; i < 256; i++) s += g_loss_part[i];
    *out_loss = 0.25f * (float)(s / ((double)N_ * (double)D_));
    *out_urate = (float)g_usage_cnt / (float)K_;
}

// ---------------- used mask from pass B ----------------
__global__ void used_kernel() {
    int i = blockIdx.x * 256 + threadIdx.x;   // grid = 128
    g_used[g_idx2[i]] = 1;
}

// ---------------- dead-code reset + steps output ----------------
__global__ void finalize_kernel(const float* __restrict__ X, const int* __restrict__ steps_in,
                                const int* __restrict__ rnd, float* __restrict__ out_emb,
                                float* __restrict__ out_steps)
{
    int k = blockIdx.x;
    int d = threadIdx.x;
    int used = g_used[k];
    float stepv = used ? 0.0f : ((float)steps_in[k] + 1.0f);
    bool dead = stepv > 100.0f;
    if (dead) {
        int r = rnd[k];
        out_emb[(size_t)k * D_ + d] = X[(size_t)r * D_ + d];
    }
    if (d == 0) out_steps[k] = dead ? 0.0f : stepv;
}

// ---------------- launch ----------------
extern "C" void kernel_launch(void* const* d_in, const int* in_sizes, int n_in,
                              void* d_out, int out_size)
{
    const float* x       = (const float*)d_in[0];
    const float* emb     = (const float*)d_in[1];
    const float* ema_cs  = (const float*)d_in[2];
    const float* ema_w   = (const float*)d_in[3];
    const float* usage   = (const float*)d_in[4];
    const int*   steps_i = (const int*)d_in[5];
    const int*   rnd     = (const int*)d_in[6];

    float* out     = (float*)d_out;
    float* o_quant = out;                         // N*D
    float* o_idx   = o_quant + (size_t)N_ * D_;   // N
    float* o_loss  = o_idx + N_;                  // 1
    float* o_emb   = o_loss + 1;                  // K*D (only 4B-aligned; scalar access only)
    float* o_cs    = o_emb + (size_t)K_ * D_;     // K
    float* o_emaw  = o_cs + K_;                   // K*D
    float* o_usage = o_emaw + (size_t)K_ * D_;    // K
    float* o_steps = o_usage + K_;                // K
    float* o_urate = o_steps + K_;                // 1

    float* embB_dev = nullptr;
    cudaGetSymbolAddress((void**)&embB_dev, g_embB);
    float* x2_dev = nullptr;
    cudaGetSymbolAddress((void**)&x2_dev, g_x2);
    float* e2a_dev = nullptr;
    cudaGetSymbolAddress((void**)&e2a_dev, g_e2a);
    float* e2b_dev = nullptr;
    cudaGetSymbolAddress((void**)&e2b_dev, g_e2b);

    static int smem_configured = 0;
    if (!smem_configured) {
        cudaFuncSetAttribute(argmin_kernel,
                             cudaFuncAttributeMaxDynamicSharedMemorySize, SMEM_ARG);
        smem_configured = 1;
    }

    init_kernel<<<(K_ * D_) / 256, 256>>>();
    rowsq_kernel<<<N_ / 8, 256>>>(x, x2_dev, N_);          // x2 (bit-critical)
    rowsq_kernel<<<K_ / 8, 256>>>(emb, e2a_dev, K_);       // e2 pass A
    argmin_kernel<<<N_ / 128, 512, SMEM_ARG>>>(x, emb, 0);
    stats_kernel<<<N_, 256>>>(x, emb, o_quant, o_idx);
    cs_kernel<<<K_ / 256, 256>>>(ema_cs, usage, o_cs, o_usage);
    emb_kernel<<<K_, 256>>>(ema_w, o_cs, o_emaw, o_emb);
    scalar_kernel<<<1, 1>>>(o_loss, o_urate);
    rowsq_kernel<<<K_ / 8, 256>>>(embB_dev, e2b_dev, K_);  // e2 pass B
    argmin_kernel<<<N_ / 128, 512, SMEM_ARG>>>(x, embB_dev, 1);
    used_kernel<<<N_ / 256, 256>>>();
    finalize_kernel<<<K_, 256>>>(x, steps_i, rnd, o_emb, o_steps);
}

// round 15
// speedup vs baseline: 1.7648x; 1.3343x over previous
#include <cuda_runtime.h>
#include <cuda_bf16.h>

// Problem constants (fixed shapes from reference setup_inputs)
#define N_ 32768
#define K_ 4096
#define D_ 256

// ---------------- device scratch (no allocations allowed) ----------------
__device__ float  g_x2[N_];           // ||x_n||^2 (XLA-style warp row-reduce bits)
__device__ float  g_e2a[K_];          // ||embedding_k||^2 (pass A)
__device__ float  g_e2b[K_];          // ||new_embedding_k||^2 (pass B)
__device__ __align__(16) float g_embB[K_ * D_];   // aligned copy of new_embedding for pass B
__device__ unsigned long long g_pack1[N_];  // packed (score,idx) argmin pass A
__device__ unsigned long long g_pack2[N_];  // packed (score,idx) argmin pass B
__device__ unsigned g_ticket[2];      // dynamic work tickets (pass A / pass B)
__device__ float  g_counts[K_];       // segment counts (pass A)
__device__ float  g_dw[K_ * D_];      // segment sum of x per code
__device__ double g_loss_part[256];   // partial commitment-loss sums
__device__ float  g_nsum;             // sum(new_cs)
__device__ int    g_used[K_];         // used mask from pass B
__device__ int    g_usage_cnt;        // count(new_usage > 0)

// ---------------- helpers ----------------
__device__ __forceinline__ unsigned long long pack_min(float f, int idx) {
    unsigned u = __float_as_uint(f);
    u = (u & 0x80000000u) ? ~u : (u | 0x80000000u);   // order-preserving key
    return ((unsigned long long)u << 32) | (unsigned)idx;
}

// packed 2xfp32 FMA (each lane rounds .rn, bit-identical to scalar FFMA)
__device__ __forceinline__ unsigned long long ffma2(unsigned long long a,
                                                    unsigned long long b,
                                                    unsigned long long c) {
    unsigned long long d;
    asm("fma.rn.f32x2 %0, %1, %2, %3;" : "=l"(d) : "l"(a), "l"(b), "l"(c));
    return d;
}

// duplicate one float into both halves of a 64-bit pair
__device__ __forceinline__ unsigned long long pack2(float v) {
    unsigned long long r;
    asm("mov.b64 %0, {%1, %1};" : "=l"(r) : "f"(v));
    return r;
}

// ---------------- init: zero all scratch (graph replays!) ----------------
__global__ void init_kernel() {
    int i = blockIdx.x * blockDim.x + threadIdx.x;
    g_dw[i] = 0.0f;
    if (i < K_) { g_counts[i] = 0.0f; g_used[i] = 0; }
    if (i < N_) { g_pack1[i] = ~0ull; g_pack2[i] = ~0ull; }
    if (i < 256) g_loss_part[i] = 0.0;
    if (i < 2) g_ticket[i] = 0u;
    if (i == 0) { g_nsum = 0.0f; g_usage_cnt = 0; }
}

// ---------------- row sum-of-squares, XLA-style warp reduce ----------------
__global__ void rowsq_kernel(const float* __restrict__ X, float* __restrict__ out, int rows) {
    int warp = (blockIdx.x * blockDim.x + threadIdx.x) >> 5;
    int lane = threadIdx.x & 31;
    if (warp >= rows) return;
    const float* row = X + (size_t)warp * D_;
    float acc = 0.0f;
    #pragma unroll
    for (int i = 0; i < 8; i++) {
        float v = row[lane + 32 * i];
        acc = __fadd_rn(acc, __fmul_rn(v, v));
    }
    #pragma unroll
    for (int o = 16; o > 0; o >>= 1)
        acc = __fadd_rn(acc, __shfl_down_sync(0xffffffffu, acc, o));
    if (lane == 0) out[warp] = acc;
}

// ---------------- fused distance-argmin SGEMM (FFMA2, persistent + dynamic tickets) ----------------
// score[n,k] = fl(fl(x2[n] - 2*dot(x_n,E_k)) + e2[k]); global argmin via atomicMin on
// packed (score,idx) u64 -> lowest score, lowest index on ties (order-invariant, bit-exact).
// 152 persistent CTAs pull units (row-tile 128 x K-slice 1024) off an atomic ticket.
// Inner datapath identical to the proven R6 loop: 128 rows stationary in smem; B streamed
// as 256-col x 32-d chunks; warp owns 16 rows (broadcast A reads); lane owns 8 cols.
#define AS_STRIDE 132
#define AS_BYTES  (256 * AS_STRIDE * 4)   // 135168
#define BS_BYTES  (32 * 256 * 4)          // 32768
#define X2S_BYTES (128 * 4)
#define SMEM_ARG  (AS_BYTES + BS_BYTES + X2S_BYTES)   // 168448
#define GRID_PERSIST 152
#define N_UNITS   1024                    // 256 row-tiles x 4 K-slices

__global__ void __launch_bounds__(256, 1)
argmin_kernel(const float* __restrict__ X, const float* __restrict__ E, int pass)
{
    extern __shared__ __align__(16) char smem[];
    float (*As)[AS_STRIDE] = (float (*)[AS_STRIDE])smem;          // [256 d][128 rows]
    float (*Bs)[256]       = (float (*)[256])(smem + AS_BYTES);   // [32 d][256 cols]
    float* x2s             = (float*)(smem + AS_BYTES + BS_BYTES);
    __shared__ unsigned s_unit;

    const float* __restrict__ e2          = pass ? g_e2b : g_e2a;
    unsigned long long* __restrict__ gout = pass ? g_pack2 : g_pack1;

    const int tid  = threadIdx.x;
    const int lane = tid & 31;
    const int warp = tid >> 5;           // 8 warps, warp owns rows warp*16..+16

    for (;;) {
        if (tid == 0) s_unit = atomicAdd(&g_ticket[pass], 1u);
        __syncthreads();                 // broadcast unit; also: all warps done with As/Bs
        unsigned u = s_unit;
        if (u >= N_UNITS) break;
        const int rowBase = (int)(u >> 2) * 128;
        const int colBase = (int)(u & 3) * (K_ / 4);

        // ---- load A transposed (per unit): X[rowBase+r][d] -> As[d][r] ----
        // warp w covers d-range w*32..w*32+31; lane indexes the row -> conflict-free STS.
        {
            #pragma unroll
            for (int rr = 0; rr < 4; rr++) {
                int r = rr * 32 + lane;
                const float* src = &X[(size_t)(rowBase + r) * D_ + warp * 32];
                #pragma unroll
                for (int q = 0; q < 8; q++) {
                    float4 v = *(const float4*)(src + q * 4);
                    As[warp * 32 + q * 4 + 0][r] = v.x;
                    As[warp * 32 + q * 4 + 1][r] = v.y;
                    As[warp * 32 + q * 4 + 2][r] = v.z;
                    As[warp * 32 + q * 4 + 3][r] = v.w;
                }
            }
            if (tid < 128) x2s[tid] = g_x2[rowBase + tid];
        }

        float rmin[16];
        int   ridx[16];
        #pragma unroll
        for (int i = 0; i < 16; i++) { rmin[i] = 3.4e38f; ridx[i] = 0; }

        for (int ctOff = 0; ctOff < K_ / 4; ctOff += 256) {
            const int ct = colBase + ctOff;
            unsigned long long acc2[8][8];
            #pragma unroll
            for (int i = 0; i < 8; i++)
                #pragma unroll
                for (int j = 0; j < 8; j++) acc2[i][j] = 0ull;

            for (int d0 = 0; d0 < D_; d0 += 32) {
                __syncthreads();   // prev chunk consumed (also orders A-load on first pass)
                // load B chunk transposed: thread owns col c = tid; conflict-free STS.
                {
                    const float* src = &E[(size_t)(ct + tid) * D_ + d0];
                    #pragma unroll
                    for (int q = 0; q < 8; q++) {
                        float4 v = *(const float4*)(src + q * 4);
                        Bs[q * 4 + 0][tid] = v.x;
                        Bs[q * 4 + 1][tid] = v.y;
                        Bs[q * 4 + 2][tid] = v.z;
                        Bs[q * 4 + 3][tid] = v.w;
                    }
                }
                __syncthreads();
                #pragma unroll 4
                for (int d = 0; d < 32; d++) {
                    const ulonglong2* ap = (const ulonglong2*)&As[d0 + d][warp * 16];
                    ulonglong2 p0 = ap[0], p1 = ap[1], p2 = ap[2], p3 = ap[3];
                    unsigned long long a2[8];
                    a2[0] = p0.x; a2[1] = p0.y; a2[2] = p1.x; a2[3] = p1.y;
                    a2[4] = p2.x; a2[5] = p2.y; a2[6] = p3.x; a2[7] = p3.y;
                    float4 bb0 = *(const float4*)&Bs[d][lane * 8];
                    float4 bb1 = *(const float4*)&Bs[d][lane * 8 + 4];
                    unsigned long long b2[8];
                    b2[0] = pack2(bb0.x); b2[1] = pack2(bb0.y);
                    b2[2] = pack2(bb0.z); b2[3] = pack2(bb0.w);
                    b2[4] = pack2(bb1.x); b2[5] = pack2(bb1.y);
                    b2[6] = pack2(bb1.z); b2[7] = pack2(bb1.w);
                    #pragma unroll
                    for (int i = 0; i < 8; i++)
                        #pragma unroll
                        for (int j = 0; j < 8; j++)
                            acc2[i][j] = ffma2(a2[i], b2[j], acc2[i][j]);
                }
            }
            // ---- fold this 256-col tile into running argmin (exact reference rounding) ----
            #pragma unroll
            for (int j = 0; j < 8; j++) {
                int col = ct + lane * 8 + j;
                float ev = __ldg(&e2[col]);
                #pragma unroll
                for (int i = 0; i < 8; i++) {
                    float xlo = x2s[warp * 16 + 2 * i];
                    float xhi = x2s[warp * 16 + 2 * i + 1];
                    float mlo = __uint_as_float((unsigned)(acc2[i][j] & 0xffffffffull));
                    float mhi = __uint_as_float((unsigned)(acc2[i][j] >> 32));
                    float sc0 = __fadd_rn(__fadd_rn(xlo, __fmul_rn(-2.0f, mlo)), ev);
                    float sc1 = __fadd_rn(__fadd_rn(xhi, __fmul_rn(-2.0f, mhi)), ev);
                    if (sc0 < rmin[2 * i])     { rmin[2 * i] = sc0;     ridx[2 * i] = col; }
                    if (sc1 < rmin[2 * i + 1]) { rmin[2 * i + 1] = sc1; ridx[2 * i + 1] = col; }
                }
            }
        }

        // ---- cross-lane reduce per row, then global merge via atomicMin ----
        #pragma unroll
        for (int rr = 0; rr < 16; rr++) {
            unsigned long long b = pack_min(rmin[rr], ridx[rr]);
            #pragma unroll
            for (int o = 16; o > 0; o >>= 1) {
                unsigned long long v = __shfl_xor_sync(0xffffffffu, b, o);
                if (v < b) b = v;
            }
            if (lane == 0) atomicMin(&gout[rowBase + warp * 16 + rr], b);
        }
    }
}

// ---------------- quantize + loss + segment sums (pass A) ----------------
__global__ void stats_kernel(const float* __restrict__ X, const float* __restrict__ E,
                             float* __restrict__ out_quant, float* __restrict__ out_idxf)
{
    int n = blockIdx.x;
    int d = threadIdx.x;
    int idx = (int)(g_pack1[n] & 0xffffffffull);
    float xv = X[(size_t)n * D_ + d];
    float q  = E[(size_t)idx * D_ + d];
    float quant = __fadd_rn(xv, __fadd_rn(q, -xv));   // fl(x + fl(q - x))
    out_quant[(size_t)n * D_ + d] = quant;
    float diff = __fadd_rn(xv, -quant);
    float v = __fmul_rn(diff, diff);
    __shared__ float sh[8];
    #pragma unroll
    for (int o = 16; o > 0; o >>= 1) v += __shfl_down_sync(0xffffffffu, v, o);
    if ((d & 31) == 0) sh[d >> 5] = v;
    __syncthreads();
    atomicAdd(&g_dw[(size_t)idx * D_ + d], xv);
    if (d == 0) {
        float s = 0.0f;
        #pragma unroll
        for (int w = 0; w < 8; w++) s += sh[w];
        atomicAdd(&g_loss_part[n & 255], (double)s);
        out_idxf[n] = (float)idx;
        atomicAdd(&g_counts[idx], 1.0f);
    }
}

// ---------------- new_cs, new_usage, n-sum, usage count ----------------
__global__ void cs_kernel(const float* __restrict__ ema_cs, const float* __restrict__ usage,
                          float* __restrict__ out_cs, float* __restrict__ out_usage)
{
    int k = blockIdx.x * 256 + threadIdx.x;   // grid = 16
    float c = g_counts[k];
    float ncs = __fadd_rn(__fmul_rn(ema_cs[k], 0.99f), __fmul_rn(0.01f, c));
    out_cs[k] = ncs;
    float nu = __fadd_rn(__fmul_rn(usage[k], 0.99f), __fmul_rn(0.01f, c));
    out_usage[k] = nu;

    float v = ncs;
    __shared__ float sh[8];
    #pragma unroll
    for (int o = 16; o > 0; o >>= 1) v += __shfl_down_sync(0xffffffffu, v, o);
    if ((threadIdx.x & 31) == 0) sh[threadIdx.x >> 5] = v;

    unsigned bal = __ballot_sync(0xffffffffu, nu > 0.0f);
    if ((threadIdx.x & 31) == 0) atomicAdd(&g_usage_cnt, __popc(bal));

    __syncthreads();
    if (threadIdx.x == 0) {
        float s = 0.0f;
        #pragma unroll
        for (int w = 0; w < 8; w++) s += sh[w];
        atomicAdd(&g_nsum, s);
    }
}

// ---------------- new_ema_w, new_embedding (to out + aligned scratch) ----------------
__global__ void emb_kernel(const float* __restrict__ ema_w, const float* __restrict__ out_cs,
                           float* __restrict__ out_ema_w, float* __restrict__ out_emb)
{
    int k = blockIdx.x;
    int d = threadIdx.x;
    float ncs = out_cs[k];
    float n = g_nsum;
    float csz = __fmul_rn(__fdiv_rn(__fadd_rn(ncs, 1e-5f),
                                    __fadd_rn(n, (float)K_ * 1e-5f)), n);
    float w = __fadd_rn(__fmul_rn(ema_w[(size_t)k * D_ + d], 0.99f),
                        __fmul_rn(0.01f, g_dw[(size_t)k * D_ + d]));
    out_ema_w[(size_t)k * D_ + d] = w;
    float e = __fdiv_rn(w, csz);
    out_emb[(size_t)k * D_ + d] = e;
    g_embB[(size_t)k * D_ + d] = e;            // aligned copy for pass-B argmin
}

// ---------------- scalars: loss, usage_rate ----------------
__global__ void scalar_kernel(float* __restrict__ out_loss, float* __restrict__ out_urate) {
    double s = 0.0;
    for (int i = 0; i < 256; i++) s += g_loss_part[i];
    *out_loss = 0.25f * (float)(s / ((double)N_ * (double)D_));
    *out_urate = (float)g_usage_cnt / (float)K_;
}

// ---------------- used mask from pass B ----------------
__global__ void used_kernel() {
    int i = blockIdx.x * 256 + threadIdx.x;   // grid = 128
    g_used[(int)(g_pack2[i] & 0xffffffffull)] = 1;
}

// ---------------- dead-code reset + steps output ----------------
__global__ void finalize_kernel(const float* __restrict__ X, const int* __restrict__ steps_in,
                                const int* __restrict__ rnd, float* __restrict__ out_emb,
                                float* __restrict__ out_steps)
{
    int k = blockIdx.x;
    int d = threadIdx.x;
    int used = g_used[k];
    float stepv = used ? 0.0f : ((float)steps_in[k] + 1.0f);
    bool dead = stepv > 100.0f;
    if (dead) {
        int r = rnd[k];
        out_emb[(size_t)k * D_ + d] = X[(size_t)r * D_ + d];
    }
    if (d == 0) out_steps[k] = dead ? 0.0f : stepv;
}

// ---------------- launch ----------------
extern "C" void kernel_launch(void* const* d_in, const int* in_sizes, int n_in,
                              void* d_out, int out_size)
{
    const float* x       = (const float*)d_in[0];
    const float* emb     = (const float*)d_in[1];
    const float* ema_cs  = (const float*)d_in[2];
    const float* ema_w   = (const float*)d_in[3];
    const float* usage   = (const float*)d_in[4];
    const int*   steps_i = (const int*)d_in[5];
    const int*   rnd     = (const int*)d_in[6];

    float* out     = (float*)d_out;
    float* o_quant = out;                         // N*D
    float* o_idx   = o_quant + (size_t)N_ * D_;   // N
    float* o_loss  = o_idx + N_;                  // 1
    float* o_emb   = o_loss + 1;                  // K*D (only 4B-aligned; scalar access only)
    float* o_cs    = o_emb + (size_t)K_ * D_;     // K
    float* o_emaw  = o_cs + K_;                   // K*D
    float* o_usage = o_emaw + (size_t)K_ * D_;    // K
    float* o_steps = o_usage + K_;                // K
    float* o_urate = o_steps + K_;                // 1

    float* embB_dev = nullptr;
    cudaGetSymbolAddress((void**)&embB_dev, g_embB);
    float* x2_dev = nullptr;
    cudaGetSymbolAddress((void**)&x2_dev, g_x2);
    float* e2a_dev = nullptr;
    cudaGetSymbolAddress((void**)&e2a_dev, g_e2a);
    float* e2b_dev = nullptr;
    cudaGetSymbolAddress((void**)&e2b_dev, g_e2b);

    static int smem_configured = 0;
    if (!smem_configured) {
        cudaFuncSetAttribute(argmin_kernel,
                             cudaFuncAttributeMaxDynamicSharedMemorySize, SMEM_ARG);
        smem_configured = 1;
    }

    init_kernel<<<(K_ * D_) / 256, 256>>>();
    rowsq_kernel<<<N_ / 8, 256>>>(x, x2_dev, N_);          // x2 (bit-critical)
    rowsq_kernel<<<K_ / 8, 256>>>(emb, e2a_dev, K_);       // e2 pass A
    argmin_kernel<<<GRID_PERSIST, 256, SMEM_ARG>>>(x, emb, 0);
    stats_kernel<<<N_, 256>>>(x, emb, o_quant, o_idx);
    cs_kernel<<<K_ / 256, 256>>>(ema_cs, usage, o_cs, o_usage);
    emb_kernel<<<K_, 256>>>(ema_w, o_cs, o_emaw, o_emb);
    scalar_kernel<<<1, 1>>>(o_loss, o_urate);
    rowsq_kernel<<<K_ / 8, 256>>>(embB_dev, e2b_dev, K_);  // e2 pass B
    argmin_kernel<<<GRID_PERSIST, 256, SMEM_ARG>>>(x, embB_dev, 1);
    used_kernel<<<N_ / 256, 256>>>();
    finalize_kernel<<<K_, 256>>>(x, steps_i, rnd, o_emb, o_steps);
}